// round 13
// baseline (speedup 1.0000x reference)
#include <cuda_runtime.h>
#include <cuda_bf16.h>
#include <cstdint>

#define BATCH 8192
#define DIM   2048
#define EPS   1e-5f
#define SLOPE 0.001f

// ---- GEMM tiling ----
#define BM 128
#define BN 128
#define BK 64
#define NT_N (DIM / BN)                      // 16 n-tiles
#define NTILES (NT_N * (BATCH / BM))         // 1024
#define GRID_P 148                           // persistent CTAs (1/SM)
#define STAGES 3
#define TILE_BYTES 16384                     // 128 rows x 128 bytes
#define STAGE_BYTES (4 * TILE_BYTES)         // Au, Av, Bu, Bv = 64 KB
#define SMEM_DYN (STAGES * STAGE_BYTES + 1024)
#define NTHREADS 512

// ---------------- scratch (__device__ globals; allocations forbidden) --------
__device__ __align__(1024) __nv_bfloat16 g_Au[(size_t)BATCH * DIM];
__device__ __align__(1024) __nv_bfloat16 g_Av[(size_t)BATCH * DIM];
__device__ __align__(1024) __nv_bfloat16 g_Wtu[(size_t)DIM * DIM];   // [n][k]
__device__ __align__(1024) __nv_bfloat16 g_Wtv[(size_t)DIM * DIM];   // [n][k]

// ---------------- helpers ----------------------------------------------------
__device__ __forceinline__ uint32_t smem_u32(const void* p) {
    uint32_t a;
    asm("{ .reg .u64 t; cvta.to.shared.u64 t, %1; cvt.u32.u64 %0, t; }" : "=r"(a) : "l"(p));
    return a;
}
#define SW128(off) ((off) ^ (((off) >> 3) & 0x70))

#define CP_ASYNC16(saddr, gptr) \
    asm volatile("cp.async.cg.shared.global [%0], [%1], 16;" :: "r"(saddr), "l"(gptr))
#define CP_COMMIT() asm volatile("cp.async.commit_group;" ::: "memory")
#define CP_WAIT1()  asm volatile("cp.async.wait_group 1;" ::: "memory")

#define LDSM4(r0, r1, r2, r3, addr)                                            \
    asm volatile("ldmatrix.sync.aligned.m8n8.x4.shared.b16 {%0,%1,%2,%3}, [%4];" \
                 : "=r"(r0), "=r"(r1), "=r"(r2), "=r"(r3) : "r"(addr))

#define MMA_BF16(C, A0, A1, A2, A3, B0, B1)                                   \
    asm volatile(                                                             \
        "mma.sync.aligned.m16n8k16.row.col.f32.bf16.bf16.f32 "                \
        "{%0,%1,%2,%3},{%4,%5,%6,%7},{%8,%9},{%0,%1,%2,%3};"                  \
        : "+f"(C[0]), "+f"(C[1]), "+f"(C[2]), "+f"(C[3])                      \
        : "r"(A0), "r"(A1), "r"(A2), "r"(A3), "r"(B0), "r"(B1))

__device__ __forceinline__ float leaky(float x) { return x >= 0.f ? x : SLOPE * x; }

// ---------------- prep: transpose both W's + LayerNorm both towers + zero ----
__global__ void prep_kernel(const float* __restrict__ xu, const float* __restrict__ xv,
                            const float* __restrict__ lnuw, const float* __restrict__ lnub,
                            const float* __restrict__ lnvw, const float* __restrict__ lnvb,
                            const float* __restrict__ Wu, const float* __restrict__ Wv,
                            __nv_bfloat16* __restrict__ Au, __nv_bfloat16* __restrict__ Av,
                            __nv_bfloat16* __restrict__ Wtu, __nv_bfloat16* __restrict__ Wtv,
                            float* __restrict__ out_zero) {
    __shared__ float shbuf[64 * 65];
    const int t = threadIdx.x;

    if (blockIdx.x < 2048) {
        float (*tile)[65] = reinterpret_cast<float (*)[65]>(shbuf);
        const int tb = blockIdx.x;
        const int zz = tb & 1;
        const int idx = tb >> 1;
        const float* W = zz ? Wv : Wu;
        __nv_bfloat16* Wt = zz ? Wtv : Wtu;
        const int bx = (idx & 31) * 64;
        const int by = (idx >> 5) * 64;
        const int tx = t & 31, ty = t >> 5;
        #pragma unroll
        for (int j = 0; j < 8; ++j) {
            const int r = ty + j * 8;
            const float* src = &W[(size_t)(by + r) * DIM + bx];
            tile[r][tx]      = src[tx];
            tile[r][tx + 32] = src[tx + 32];
        }
        __syncthreads();
        #pragma unroll
        for (int j = 0; j < 8; ++j) {
            const int r = ty + j * 8;
            __nv_bfloat162* dst = reinterpret_cast<__nv_bfloat162*>(
                &Wt[(size_t)(bx + r) * DIM + by]);
            dst[tx] = __floats2bfloat162_rn(tile[2 * tx][r], tile[2 * tx + 1][r]);
        }
        return;
    }

    const int id   = blockIdx.x - 2048;
    const int towr = id & 1;
    const int row  = id >> 1;
    const float* x = towr ? xv : xu;
    const float* w = towr ? lnvw : lnuw;
    const float* b = towr ? lnvb : lnub;
    __nv_bfloat16* outp = towr ? Av : Au;
    if (!towr && t == 0) out_zero[row] = 0.0f;

    float* ss    = shbuf;
    float* sq    = shbuf + 8;
    float* stats = shbuf + 16;

    const float4* xr = reinterpret_cast<const float4*>(x + (size_t)row * DIM);
    float4 v0 = xr[t];
    float4 v1 = xr[t + 256];
    float s = v0.x + v0.y + v0.z + v0.w + v1.x + v1.y + v1.z + v1.w;
    float q = v0.x*v0.x + v0.y*v0.y + v0.z*v0.z + v0.w*v0.w
            + v1.x*v1.x + v1.y*v1.y + v1.z*v1.z + v1.w*v1.w;
    #pragma unroll
    for (int off = 16; off; off >>= 1) {
        s += __shfl_xor_sync(0xffffffffu, s, off);
        q += __shfl_xor_sync(0xffffffffu, q, off);
    }
    const int wid = t >> 5, lane = t & 31;
    if (lane == 0) { ss[wid] = s; sq[wid] = q; }
    __syncthreads();
    if (t == 0) {
        float S = 0.f, Q = 0.f;
        #pragma unroll
        for (int i = 0; i < 8; ++i) { S += ss[i]; Q += sq[i]; }
        float mu  = S * (1.0f / DIM);
        float var = Q * (1.0f / DIM) - mu * mu;
        stats[0] = mu;
        stats[1] = rsqrtf(var + EPS);
    }
    __syncthreads();
    const float mu = stats[0], rs = stats[1];
    const float4* wr = reinterpret_cast<const float4*>(w);
    const float4* br = reinterpret_cast<const float4*>(b);
    __nv_bfloat162* o = reinterpret_cast<__nv_bfloat162*>(outp + (size_t)row * DIM);
    {
        float4 ww = wr[t], bb = br[t];
        o[2*t  ] = __floats2bfloat162_rn((v0.x-mu)*rs*ww.x + bb.x, (v0.y-mu)*rs*ww.y + bb.y);
        o[2*t+1] = __floats2bfloat162_rn((v0.z-mu)*rs*ww.z + bb.z, (v0.w-mu)*rs*ww.w + bb.w);
    }
    {
        float4 ww = wr[t+256], bb = br[t+256];
        o[2*(t+256)  ] = __floats2bfloat162_rn((v1.x-mu)*rs*ww.x + bb.x, (v1.y-mu)*rs*ww.y + bb.y);
        o[2*(t+256)+1] = __floats2bfloat162_rn((v1.z-mu)*rs*ww.z + bb.z, (v1.w-mu)*rs*ww.w + bb.w);
    }
}

// ---------------- persistent fused dual GEMM + epilogue ----------------------
// 512 threads, 16 warps. Warps 0-7: u tower; 8-15: v tower. Warp tile 32x64
// (tower warp grid: 4 along M x 2 along N). Grid = 148 persistent CTAs with a
// continuous cross-tile cp.async pipeline (stage = global chunk counter % 3).
__global__ void __launch_bounds__(NTHREADS, 1) fused_gemm_kernel(
    const float* __restrict__ bias_u, const float* __restrict__ bias_v,
    float* __restrict__ out) {
    extern __shared__ char smem[];
    const uint32_t sbase0 = smem_u32(smem);
    const uint32_t sbase = (sbase0 + 1023u) & ~1023u;
    char* smem_al = smem + (sbase - sbase0);
    const int tid   = threadIdx.x;
    const int warp  = tid >> 5;
    const int lane  = tid & 31;
    const int g     = lane >> 2;
    const int t4    = lane & 3;
    const int tower = warp >> 3;          // 0 = u, 1 = v
    const int wq    = warp & 7;
    const int wm    = (wq & 3) * 32;      // 4 warps along M
    const int wn    = (wq >> 2) * 64;     // 2 warps along N
    const int bid   = blockIdx.x;

    const uint32_t a_tile = tower * TILE_BYTES;
    const uint32_t b_tile = 2 * TILE_BYTES + tower * TILE_BYTES;

    // ldmatrix per-lane address components
    const int a_row = lane & 15;
    const int a_kb  = (lane >> 4) << 4;
    const int b_row = (lane & 7) + ((lane >> 4) << 3);
    const int b_kb  = ((lane >> 3) & 1) << 4;

    // ---- prologue: load chunks 0 and 1 (kt 0,1 of first tile) ----
    {
        const int m0p = (bid >> 4) * BM;
        const int n0p = (bid & 15) * BN;
        #pragma unroll
        for (int c0 = 0; c0 < 2; ++c0) {
            const uint32_t stb = sbase + c0 * STAGE_BYTES;   // stage c0%3 = c0
            const size_t kg = (size_t)c0 * BK;
            #pragma unroll
            for (int p = 0; p < 2; ++p) {
                const int c = tid + p * 512;
                const int r = c >> 3, bo = (c & 7) * 16;
                const uint32_t so = SW128((uint32_t)(r * 128 + bo));
                const size_t ga = (size_t)(m0p + r) * DIM + kg + (bo >> 1);
                const size_t gb = (size_t)(n0p + r) * DIM + kg + (bo >> 1);
                CP_ASYNC16(stb + so,                  &g_Au[ga]);
                CP_ASYNC16(stb + TILE_BYTES + so,     &g_Av[ga]);
                CP_ASYNC16(stb + 2 * TILE_BYTES + so, &g_Wtu[gb]);
                CP_ASYNC16(stb + 3 * TILE_BYTES + so, &g_Wtv[gb]);
            }
            CP_COMMIT();
        }
    }

    int lc = 0;   // global chunk counter (consumed)
    for (int tg = bid; tg < NTILES; tg += GRID_P) {
        const int m0 = (tg >> 4) * BM;
        const int n0 = (tg & 15) * BN;

        float acc[2][8][4];
        #pragma unroll
        for (int i = 0; i < 2; ++i)
            #pragma unroll
            for (int j = 0; j < 8; ++j)
                #pragma unroll
                for (int k = 0; k < 4; ++k) acc[i][j][k] = 0.f;

        for (int kt = 0; kt < 32; ++kt, ++lc) {
            CP_WAIT1();
            __syncthreads();
            const uint32_t stb = sbase + (lc % 3) * STAGE_BYTES;

            // prefetch target: chunk lc+2
            const int cpf   = lc + 2;
            const int tg_pf = bid + (cpf >> 5) * GRID_P;
            const bool dopf = (tg_pf < NTILES);
            const uint32_t stb_pf = sbase + (cpf % 3) * STAGE_BYTES;
            const int m0p = (tg_pf >> 4) * BM;
            const int n0p = (tg_pf & 15) * BN;
            const size_t kgp = (size_t)(cpf & 31) * BK;

            #pragma unroll
            for (int ks = 0; ks < 4; ++ks) {
                // B fragments: 64 N-rows = 4 x ldmatrix.x4
                uint32_t bfr[8][2];
                #pragma unroll
                for (int nt = 0; nt < 4; ++nt) {
                    const int nrow = wn + nt * 16 + b_row;
                    const uint32_t off = SW128((uint32_t)(nrow * 128 + ks * 32 + b_kb));
                    uint32_t r0, r1, r2, r3;
                    LDSM4(r0, r1, r2, r3, stb + b_tile + off);
                    bfr[2*nt][0] = r0; bfr[2*nt][1] = r1;
                    bfr[2*nt+1][0] = r2; bfr[2*nt+1][1] = r3;
                }
                // half of the next-chunk prefetch at ks=0 and ks=1
                if (dopf && ks < 2) {
                    const int c = tid + ks * 512;
                    const int r = c >> 3, bo = (c & 7) * 16;
                    const uint32_t so = SW128((uint32_t)(r * 128 + bo));
                    const size_t ga = (size_t)(m0p + r) * DIM + kgp + (bo >> 1);
                    const size_t gb = (size_t)(n0p + r) * DIM + kgp + (bo >> 1);
                    CP_ASYNC16(stb_pf + so,                  &g_Au[ga]);
                    CP_ASYNC16(stb_pf + TILE_BYTES + so,     &g_Av[ga]);
                    CP_ASYNC16(stb_pf + 2 * TILE_BYTES + so, &g_Wtu[gb]);
                    CP_ASYNC16(stb_pf + 3 * TILE_BYTES + so, &g_Wtv[gb]);
                }
                // A fragments + MMAs: 32 M-rows = 2 x ldmatrix.x4
                #pragma unroll
                for (int mt = 0; mt < 2; ++mt) {
                    const int arow = wm + mt * 16 + a_row;
                    const uint32_t off = SW128((uint32_t)(arow * 128 + ks * 32 + a_kb));
                    uint32_t a0, a1, a2, a3;
                    LDSM4(a0, a1, a2, a3, stb + a_tile + off);
                    #pragma unroll
                    for (int j = 0; j < 8; ++j)
                        MMA_BF16(acc[mt][j], a0, a1, a2, a3, bfr[j][0], bfr[j][1]);
                }
            }
            CP_COMMIT();
        }

        // ---------------- epilogue (in the just-freed stage buffer) ----------
        float* xbuf = reinterpret_cast<float*>(smem_al + ((lc - 1) % 3) * STAGE_BYTES);
        __syncthreads();   // all LDSM reads of stage (lc-1)%3 complete

        if (tower == 1) {
            float* dst = xbuf + (wq * 64) * 32 + lane;   // [wq][reg][lane], 64 KB
            #pragma unroll
            for (int mt = 0; mt < 2; ++mt)
                #pragma unroll
                for (int j = 0; j < 8; ++j) {
                    const int ncol = n0 + wn + j * 8 + 2 * t4;
                    const float b0 = bias_v[ncol], b1 = bias_v[ncol + 1];
                    const int r = mt * 32 + j * 4;
                    dst[(r + 0) * 32] = leaky(acc[mt][j][0] + b0);
                    dst[(r + 1) * 32] = leaky(acc[mt][j][1] + b1);
                    dst[(r + 2) * 32] = leaky(acc[mt][j][2] + b0);
                    dst[(r + 3) * 32] = leaky(acc[mt][j][3] + b1);
                }
        }
        __syncthreads();
        if (tower == 0) {
            const float* src = xbuf + (wq * 64) * 32 + lane;
            #pragma unroll
            for (int mt = 0; mt < 2; ++mt) {
                float p0 = 0.f, p1 = 0.f;
                #pragma unroll
                for (int j = 0; j < 8; ++j) {
                    const int ncol = n0 + wn + j * 8 + 2 * t4;
                    const float b0 = bias_u[ncol], b1 = bias_u[ncol + 1];
                    const int r = mt * 32 + j * 4;
                    p0 += leaky(acc[mt][j][0] + b0) * src[(r + 0) * 32];
                    p0 += leaky(acc[mt][j][1] + b1) * src[(r + 1) * 32];
                    p1 += leaky(acc[mt][j][2] + b0) * src[(r + 2) * 32];
                    p1 += leaky(acc[mt][j][3] + b1) * src[(r + 3) * 32];
                }
                p0 += __shfl_xor_sync(0xffffffffu, p0, 1);
                p0 += __shfl_xor_sync(0xffffffffu, p0, 2);
                p1 += __shfl_xor_sync(0xffffffffu, p1, 1);
                p1 += __shfl_xor_sync(0xffffffffu, p1, 2);
                if (t4 == 0) {
                    const int r = m0 + wm + mt * 16 + g;
                    atomicAdd(&out[r], p0);
                    atomicAdd(&out[r + 8], p1);
                }
            }
        }
        // next tile's kt0 __syncthreads orders xbuf reads before any cp.async
        // that could overwrite this stage (chunk lc+2, same stage index).
    }
}

// ---------------- launch -----------------------------------------------------
extern "C" void kernel_launch(void* const* d_in, const int* in_sizes, int n_in,
                              void* d_out, int out_size) {
    (void)in_sizes; (void)n_in; (void)out_size;
    const float* u      = (const float*)d_in[0];
    const float* v      = (const float*)d_in[1];
    const float* ln_u_w = (const float*)d_in[2];
    const float* ln_u_b = (const float*)d_in[3];
    const float* ln_v_w = (const float*)d_in[4];
    const float* ln_v_b = (const float*)d_in[5];
    const float* W_u    = (const float*)d_in[6];
    const float* b_u    = (const float*)d_in[7];
    const float* W_v    = (const float*)d_in[8];
    const float* b_v    = (const float*)d_in[9];
    float* out = (float*)d_out;

    void *pAu, *pAv, *pWtu, *pWtv;
    cudaGetSymbolAddress(&pAu, g_Au);
    cudaGetSymbolAddress(&pAv, g_Av);
    cudaGetSymbolAddress(&pWtu, g_Wtu);
    cudaGetSymbolAddress(&pWtv, g_Wtv);

    prep_kernel<<<2048 + 2 * BATCH, 256>>>(
        u, v, ln_u_w, ln_u_b, ln_v_w, ln_v_b, W_u, W_v,
        (__nv_bfloat16*)pAu, (__nv_bfloat16*)pAv,
        (__nv_bfloat16*)pWtu, (__nv_bfloat16*)pWtv, out);

    cudaFuncSetAttribute(fused_gemm_kernel,
                         cudaFuncAttributeMaxDynamicSharedMemorySize, SMEM_DYN);
    fused_gemm_kernel<<<GRID_P, NTHREADS, SMEM_DYN>>>(b_u, b_v, out);
}

// round 14
// speedup vs baseline: 1.1565x; 1.1565x over previous
#include <cuda_runtime.h>
#include <cuda_bf16.h>
#include <cstdint>

#define BATCH 8192
#define DIM   2048
#define EPS   1e-5f
#define SLOPE 0.001f

// ---- GEMM tiling ----
#define BM 128
#define BN 128
#define BK 64
#define NT_N (DIM / BN)                      // 16 n-tiles
#define NTILES (NT_N * (BATCH / BM))         // 1024
#define GRID_P 148                           // persistent CTAs (1/SM)
#define STAGES 3
#define TILE_BYTES 16384                     // 128 rows x 128 bytes
#define STAGE_BYTES (4 * TILE_BYTES)         // Au, Av, Bu, Bv = 64 KB
#define SMEM_DYN (STAGES * STAGE_BYTES + 1024)

// ---------------- scratch (__device__ globals; allocations forbidden) --------
__device__ __align__(1024) __nv_bfloat16 g_Au[(size_t)BATCH * DIM];
__device__ __align__(1024) __nv_bfloat16 g_Av[(size_t)BATCH * DIM];
__device__ __align__(1024) __nv_bfloat16 g_Wtu[(size_t)DIM * DIM];   // [n][k]
__device__ __align__(1024) __nv_bfloat16 g_Wtv[(size_t)DIM * DIM];   // [n][k]

// ---------------- helpers ----------------------------------------------------
__device__ __forceinline__ uint32_t smem_u32(const void* p) {
    uint32_t a;
    asm("{ .reg .u64 t; cvta.to.shared.u64 t, %1; cvt.u32.u64 %0, t; }" : "=r"(a) : "l"(p));
    return a;
}
#define SW128(off) ((off) ^ (((off) >> 3) & 0x70))

#define CP_ASYNC16(saddr, gptr) \
    asm volatile("cp.async.cg.shared.global [%0], [%1], 16;" :: "r"(saddr), "l"(gptr))
#define CP_COMMIT() asm volatile("cp.async.commit_group;" ::: "memory")
#define CP_WAIT1()  asm volatile("cp.async.wait_group 1;" ::: "memory")
#define BAR_GRP(id) asm volatile("bar.sync %0, 128;" :: "r"(id) : "memory")

#define LDSM4(r0, r1, r2, r3, addr)                                            \
    asm volatile("ldmatrix.sync.aligned.m8n8.x4.shared.b16 {%0,%1,%2,%3}, [%4];" \
                 : "=r"(r0), "=r"(r1), "=r"(r2), "=r"(r3) : "r"(addr))

#define MMA_BF16(C, A0, A1, A2, A3, B0, B1)                                   \
    asm volatile(                                                             \
        "mma.sync.aligned.m16n8k16.row.col.f32.bf16.bf16.f32 "                \
        "{%0,%1,%2,%3},{%4,%5,%6,%7},{%8,%9},{%0,%1,%2,%3};"                  \
        : "+f"(C[0]), "+f"(C[1]), "+f"(C[2]), "+f"(C[3])                      \
        : "r"(A0), "r"(A1), "r"(A2), "r"(A3), "r"(B0), "r"(B1))

__device__ __forceinline__ float leaky(float x) { return x >= 0.f ? x : SLOPE * x; }

// ---------------- prep: transpose both W's + LayerNorm both towers + zero ----
__global__ void prep_kernel(const float* __restrict__ xu, const float* __restrict__ xv,
                            const float* __restrict__ lnuw, const float* __restrict__ lnub,
                            const float* __restrict__ lnvw, const float* __restrict__ lnvb,
                            const float* __restrict__ Wu, const float* __restrict__ Wv,
                            __nv_bfloat16* __restrict__ Au, __nv_bfloat16* __restrict__ Av,
                            __nv_bfloat16* __restrict__ Wtu, __nv_bfloat16* __restrict__ Wtv,
                            float* __restrict__ out_zero) {
    __shared__ float shbuf[64 * 65];
    const int t = threadIdx.x;

    if (blockIdx.x < 2048) {
        float (*tile)[65] = reinterpret_cast<float (*)[65]>(shbuf);
        const int tb = blockIdx.x;
        const int zz = tb & 1;
        const int idx = tb >> 1;
        const float* W = zz ? Wv : Wu;
        __nv_bfloat16* Wt = zz ? Wtv : Wtu;
        const int bx = (idx & 31) * 64;
        const int by = (idx >> 5) * 64;
        const int tx = t & 31, ty = t >> 5;
        #pragma unroll
        for (int j = 0; j < 8; ++j) {
            const int r = ty + j * 8;
            const float* src = &W[(size_t)(by + r) * DIM + bx];
            tile[r][tx]      = src[tx];
            tile[r][tx + 32] = src[tx + 32];
        }
        __syncthreads();
        #pragma unroll
        for (int j = 0; j < 8; ++j) {
            const int r = ty + j * 8;
            __nv_bfloat162* dst = reinterpret_cast<__nv_bfloat162*>(
                &Wt[(size_t)(bx + r) * DIM + by]);
            dst[tx] = __floats2bfloat162_rn(tile[2 * tx][r], tile[2 * tx + 1][r]);
        }
        return;
    }

    const int id   = blockIdx.x - 2048;
    const int towr = id & 1;
    const int row  = id >> 1;
    const float* x = towr ? xv : xu;
    const float* w = towr ? lnvw : lnuw;
    const float* b = towr ? lnvb : lnub;
    __nv_bfloat16* outp = towr ? Av : Au;
    if (!towr && t == 0) out_zero[row] = 0.0f;

    float* ss    = shbuf;
    float* sq    = shbuf + 8;
    float* stats = shbuf + 16;

    const float4* xr = reinterpret_cast<const float4*>(x + (size_t)row * DIM);
    float4 v0 = xr[t];
    float4 v1 = xr[t + 256];
    float s = v0.x + v0.y + v0.z + v0.w + v1.x + v1.y + v1.z + v1.w;
    float q = v0.x*v0.x + v0.y*v0.y + v0.z*v0.z + v0.w*v0.w
            + v1.x*v1.x + v1.y*v1.y + v1.z*v1.z + v1.w*v1.w;
    #pragma unroll
    for (int off = 16; off; off >>= 1) {
        s += __shfl_xor_sync(0xffffffffu, s, off);
        q += __shfl_xor_sync(0xffffffffu, q, off);
    }
    const int wid = t >> 5, lane = t & 31;
    if (lane == 0) { ss[wid] = s; sq[wid] = q; }
    __syncthreads();
    if (t == 0) {
        float S = 0.f, Q = 0.f;
        #pragma unroll
        for (int i = 0; i < 8; ++i) { S += ss[i]; Q += sq[i]; }
        float mu  = S * (1.0f / DIM);
        float var = Q * (1.0f / DIM) - mu * mu;
        stats[0] = mu;
        stats[1] = rsqrtf(var + EPS);
    }
    __syncthreads();
    const float mu = stats[0], rs = stats[1];
    const float4* wr = reinterpret_cast<const float4*>(w);
    const float4* br = reinterpret_cast<const float4*>(b);
    __nv_bfloat162* o = reinterpret_cast<__nv_bfloat162*>(outp + (size_t)row * DIM);
    {
        float4 ww = wr[t], bb = br[t];
        o[2*t  ] = __floats2bfloat162_rn((v0.x-mu)*rs*ww.x + bb.x, (v0.y-mu)*rs*ww.y + bb.y);
        o[2*t+1] = __floats2bfloat162_rn((v0.z-mu)*rs*ww.z + bb.z, (v0.w-mu)*rs*ww.w + bb.w);
    }
    {
        float4 ww = wr[t+256], bb = br[t+256];
        o[2*(t+256)  ] = __floats2bfloat162_rn((v1.x-mu)*rs*ww.x + bb.x, (v1.y-mu)*rs*ww.y + bb.y);
        o[2*(t+256)+1] = __floats2bfloat162_rn((v1.z-mu)*rs*ww.z + bb.z, (v1.w-mu)*rs*ww.w + bb.w);
    }
}

// ---------------- persistent fused dual GEMM + epilogue ----------------------
// 256 threads, 8 warps. Warps 0-3 (threads 0-127): u tower; warps 4-7: v tower.
// Warp tile 64x64 (2x2 per tower). Each tower group loads ONLY its own two
// tiles and synchronizes on its own named barrier -> the two pipelines are
// decoupled (disjoint smem regions). Full-CTA syncs only around the epilogue.
__global__ void __launch_bounds__(256, 1) fused_gemm_kernel(
    const float* __restrict__ bias_u, const float* __restrict__ bias_v,
    float* __restrict__ out) {
    extern __shared__ char smem[];
    const uint32_t sbase0 = smem_u32(smem);
    const uint32_t sbase = (sbase0 + 1023u) & ~1023u;
    char* smem_al = smem + (sbase - sbase0);
    const int tid   = threadIdx.x;
    const int warp  = tid >> 5;
    const int lane  = tid & 31;
    const int g     = lane >> 2;
    const int t4    = lane & 3;
    const int tower = warp >> 2;          // 0 = u, 1 = v
    const int gtid  = tid & 127;          // thread id within tower group
    const int wq    = warp & 3;
    const int wm    = (wq & 1) * 64;      // 2 warps along M
    const int wn    = (wq >> 1) * 64;     // 2 warps along N
    const int bid   = blockIdx.x;
    const int barid = 1 + tower;

    const uint32_t a_tile = tower * TILE_BYTES;                    // Au or Av
    const uint32_t b_tile = 2 * TILE_BYTES + tower * TILE_BYTES;   // Bu or Bv
    const __nv_bfloat16* gA = tower ? g_Av : g_Au;
    const __nv_bfloat16* gB = tower ? g_Wtv : g_Wtu;

    // ldmatrix per-lane address components
    const int a_row = lane & 15;
    const int a_kb  = (lane >> 4) << 4;
    const int b_row = (lane & 7) + ((lane >> 4) << 3);
    const int b_kb  = ((lane >> 3) & 1) << 4;

    // ---- prologue: load chunks 0 and 1 of own tower's tiles ----
    {
        const int m0p = (bid >> 4) * BM;
        const int n0p = (bid & 15) * BN;
        #pragma unroll
        for (int c0 = 0; c0 < 2; ++c0) {
            const uint32_t stb = sbase + c0 * STAGE_BYTES;   // stage c0%3 = c0
            const size_t kg = (size_t)c0 * BK;
            #pragma unroll
            for (int p = 0; p < 8; ++p) {
                const int c = gtid + p * 128;
                const int r = c >> 3, bo = (c & 7) * 16;
                const uint32_t so = SW128((uint32_t)(r * 128 + bo));
                CP_ASYNC16(stb + a_tile + so, &gA[(size_t)(m0p + r) * DIM + kg + (bo >> 1)]);
                CP_ASYNC16(stb + b_tile + so, &gB[(size_t)(n0p + r) * DIM + kg + (bo >> 1)]);
            }
            CP_COMMIT();
        }
    }

    int lc = 0;   // global chunk counter (consumed)
    for (int tg = bid; tg < NTILES; tg += GRID_P) {
        const int m0 = (tg >> 4) * BM;
        const int n0 = (tg & 15) * BN;

        float acc[4][8][4];
        #pragma unroll
        for (int i = 0; i < 4; ++i)
            #pragma unroll
            for (int j = 0; j < 8; ++j)
                #pragma unroll
                for (int k = 0; k < 4; ++k) acc[i][j][k] = 0.f;

        for (int kt = 0; kt < 32; ++kt, ++lc) {
            CP_WAIT1();            // own group's commits: stage lc data (own tiles)
            BAR_GRP(barid);        // own tower group only
            const uint32_t stb = sbase + (lc % 3) * STAGE_BYTES;

            // prefetch target: chunk lc+2 (own tower tiles only)
            const int cpf   = lc + 2;
            const int tg_pf = bid + (cpf >> 5) * GRID_P;
            const bool dopf = (tg_pf < NTILES);
            const uint32_t stb_pf = sbase + (cpf % 3) * STAGE_BYTES;
            const int m0p = (tg_pf >> 4) * BM;
            const int n0p = (tg_pf & 15) * BN;
            const size_t kgp = (size_t)(cpf & 31) * BK;

            #pragma unroll
            for (int ks = 0; ks < 4; ++ks) {
                // B fragments: 64 N-rows = 4 x ldmatrix.x4
                uint32_t bfr[8][2];
                #pragma unroll
                for (int nt = 0; nt < 4; ++nt) {
                    const int nrow = wn + nt * 16 + b_row;
                    const uint32_t off = SW128((uint32_t)(nrow * 128 + ks * 32 + b_kb));
                    uint32_t r0, r1, r2, r3;
                    LDSM4(r0, r1, r2, r3, stb + b_tile + off);
                    bfr[2*nt][0] = r0; bfr[2*nt][1] = r1;
                    bfr[2*nt+1][0] = r2; bfr[2*nt+1][1] = r3;
                }
                // quarter of next-chunk prefetch per ks (2 pairs of 16B chunks)
                if (dopf) {
                    #pragma unroll
                    for (int pp = 0; pp < 2; ++pp) {
                        const int c = gtid + (ks * 2 + pp) * 128;
                        const int r = c >> 3, bo = (c & 7) * 16;
                        const uint32_t so = SW128((uint32_t)(r * 128 + bo));
                        CP_ASYNC16(stb_pf + a_tile + so,
                                   &gA[(size_t)(m0p + r) * DIM + kgp + (bo >> 1)]);
                        CP_ASYNC16(stb_pf + b_tile + so,
                                   &gB[(size_t)(n0p + r) * DIM + kgp + (bo >> 1)]);
                    }
                }
                // A fragments + MMAs: 64 M-rows = 4 x ldmatrix.x4
                #pragma unroll
                for (int mt = 0; mt < 4; ++mt) {
                    const int arow = wm + mt * 16 + a_row;
                    const uint32_t off = SW128((uint32_t)(arow * 128 + ks * 32 + a_kb));
                    uint32_t a0, a1, a2, a3;
                    LDSM4(a0, a1, a2, a3, stb + a_tile + off);
                    #pragma unroll
                    for (int j = 0; j < 8; ++j)
                        MMA_BF16(acc[mt][j], a0, a1, a2, a3, bfr[j][0], bfr[j][1]);
                }
            }
            CP_COMMIT();
        }

        // ---------------- epilogue (in the just-freed stage buffer) ----------
        float* xbuf = reinterpret_cast<float*>(smem_al + ((lc - 1) % 3) * STAGE_BYTES);
        __syncthreads();   // full CTA: both groups done reading stage (lc-1)%3

        if (tower == 1) {
            float* dst = xbuf + (wq * 128) * 32 + lane;   // [wq][reg][lane]
            #pragma unroll
            for (int mt = 0; mt < 4; ++mt)
                #pragma unroll
                for (int j = 0; j < 8; ++j) {
                    const int ncol = n0 + wn + j * 8 + 2 * t4;
                    const float b0 = bias_v[ncol], b1 = bias_v[ncol + 1];
                    const int r = mt * 32 + j * 4;
                    dst[(r + 0) * 32] = leaky(acc[mt][j][0] + b0);
                    dst[(r + 1) * 32] = leaky(acc[mt][j][1] + b1);
                    dst[(r + 2) * 32] = leaky(acc[mt][j][2] + b0);
                    dst[(r + 3) * 32] = leaky(acc[mt][j][3] + b1);
                }
        }
        __syncthreads();
        if (tower == 0) {
            const float* src = xbuf + (wq * 128) * 32 + lane;
            #pragma unroll
            for (int mt = 0; mt < 4; ++mt) {
                float p0 = 0.f, p1 = 0.f;
                #pragma unroll
                for (int j = 0; j < 8; ++j) {
                    const int ncol = n0 + wn + j * 8 + 2 * t4;
                    const float b0 = bias_u[ncol], b1 = bias_u[ncol + 1];
                    const int r = mt * 32 + j * 4;
                    p0 += leaky(acc[mt][j][0] + b0) * src[(r + 0) * 32];
                    p0 += leaky(acc[mt][j][1] + b1) * src[(r + 1) * 32];
                    p1 += leaky(acc[mt][j][2] + b0) * src[(r + 2) * 32];
                    p1 += leaky(acc[mt][j][3] + b1) * src[(r + 3) * 32];
                }
                p0 += __shfl_xor_sync(0xffffffffu, p0, 1);
                p0 += __shfl_xor_sync(0xffffffffu, p0, 2);
                p1 += __shfl_xor_sync(0xffffffffu, p1, 1);
                p1 += __shfl_xor_sync(0xffffffffu, p1, 2);
                if (t4 == 0) {
                    const int r = m0 + wm + mt * 16 + g;
                    atomicAdd(&out[r], p0);
                    atomicAdd(&out[r + 8], p1);
                }
            }
        }
        // full CTA: xbuf reads done before EITHER group's next prefetch can
        // overwrite this stage (groups are decoupled in the mainloop).
        __syncthreads();
    }
}

// ---------------- launch -----------------------------------------------------
extern "C" void kernel_launch(void* const* d_in, const int* in_sizes, int n_in,
                              void* d_out, int out_size) {
    (void)in_sizes; (void)n_in; (void)out_size;
    const float* u      = (const float*)d_in[0];
    const float* v      = (const float*)d_in[1];
    const float* ln_u_w = (const float*)d_in[2];
    const float* ln_u_b = (const float*)d_in[3];
    const float* ln_v_w = (const float*)d_in[4];
    const float* ln_v_b = (const float*)d_in[5];
    const float* W_u    = (const float*)d_in[6];
    const float* b_u    = (const float*)d_in[7];
    const float* W_v    = (const float*)d_in[8];
    const float* b_v    = (const float*)d_in[9];
    float* out = (float*)d_out;

    void *pAu, *pAv, *pWtu, *pWtv;
    cudaGetSymbolAddress(&pAu, g_Au);
    cudaGetSymbolAddress(&pAv, g_Av);
    cudaGetSymbolAddress(&pWtu, g_Wtu);
    cudaGetSymbolAddress(&pWtv, g_Wtv);

    prep_kernel<<<2048 + 2 * BATCH, 256>>>(
        u, v, ln_u_w, ln_u_b, ln_v_w, ln_v_b, W_u, W_v,
        (__nv_bfloat16*)pAu, (__nv_bfloat16*)pAv,
        (__nv_bfloat16*)pWtu, (__nv_bfloat16*)pWtv, out);

    cudaFuncSetAttribute(fused_gemm_kernel,
                         cudaFuncAttributeMaxDynamicSharedMemorySize, SMEM_DYN);
    fused_gemm_kernel<<<GRID_P, 256, SMEM_DYN>>>(b_u, b_v, out);
}